// round 15
// baseline (speedup 1.0000x reference)
#include <cuda_runtime.h>
#include <cuda_bf16.h>

// GridSpatialIntegral: input [B=64, C=2, WY=512, WX=512] fp32.
//   out[:,0,:,:] = cumsum over x of in[:,0,:,:]
//   out[:,1,:,:] = cumsum over y of in[:,1,:,:]
//
// R14 experiment: float2 channel-1 (LDG.64 doubles in-flight bytes per
// outstanding load slot). 1024-thread blocks, 32 warps:
//   blocks [0, 512)      : channel-1. Block owns 64 columns x 512 rows.
//                          warp w owns 16-row segment w; thread owns a
//                          float2 column pair. totals via smem (float2).
//   blocks [512, 1536)   : channel-0 row scans (warp per row, 32 rows/blk),
//                          lane-contiguous float4 loads (champion path).

#define B   64
#define WY  512
#define WX  512

#define CH1_BLOCKS 512                 // 32768 cols / 64 per block
#define CH0_BLOCKS 1024                // 32768 rows / 32 warps-per-block
#define TOTAL_BLOCKS (CH1_BLOCKS + CH0_BLOCKS)
#define THREADS 1024

__device__ __forceinline__ float warp_incl_scan(float v, int lane) {
    #pragma unroll
    for (int d = 1; d < 32; d <<= 1) {
        float n = __shfl_up_sync(0xffffffffu, v, d);
        if (lane >= d) v += n;
    }
    return v;
}

__global__ __launch_bounds__(THREADS, 1)
void grid_spatial_integral_kernel(const float* __restrict__ in,
                                  float* __restrict__ out) {
    const int bx = blockIdx.x;
    __shared__ float2 seg_totals[32][32];

    if (bx < CH1_BLOCKS) {
        // ---------------- Channel 1: cumsum along y (float2) ------------
        // block -> (batch, 64-column group). warp -> 16-row segment.
        const int lane = threadIdx.x & 31;
        const int seg  = threadIdx.x >> 5;          // 0..31
        const int b    = bx >> 3;                   // 8 col-groups per batch
        const int xg   = bx & 7;
        const int x    = xg * 64 + lane * 2;        // even column, 0..510

        const int base = ((b * 2 + 1) * WY + seg * 16) * WX + x;
        const float2* __restrict__ p = (const float2*)(in  + base);
        float2*       __restrict__ q = (float2*)(out + base);

        // load 16 rows of float2 (256B per warp instruction)
        float2 v[16];
        #pragma unroll
        for (int k = 0; k < 16; ++k)
            v[k] = __ldcs(p + k * (WX / 2));

        // in-register inclusive prefix over this segment (per component)
        #pragma unroll
        for (int k = 1; k < 16; ++k) {
            v[k].x += v[k - 1].x;
            v[k].y += v[k - 1].y;
        }

        // publish segment total, gather carry from lower segments
        seg_totals[seg][lane] = v[15];
        __syncthreads();

        float cx = 0.0f, cy = 0.0f;
        #pragma unroll
        for (int s = 0; s < 31; ++s)
            if (s < seg) {
                float2 t = seg_totals[s][lane];
                cx += t.x; cy += t.y;
            }

        #pragma unroll
        for (int k = 0; k < 16; ++k) {
            float2 o;
            o.x = v[k].x + cx;
            o.y = v[k].y + cy;
            __stcs(q + k * (WX / 2), o);
        }
    } else {
        // ---------------- Channel 0: cumsum along x (champion path) -----
        // warp per 512-float row; lane-contiguous float4 loads.
        const int idx  = bx - CH1_BLOCKS;           // 0..1023
        const int wid  = threadIdx.x >> 5;          // 0..31
        const int lane = threadIdx.x & 31;
        const int row  = idx * 32 + wid;            // 0..32767
        const int b    = row >> 9;
        const int y    = row & 511;

        const int base = ((b * 2 + 0) * WY + y) * WX;
        const float4* __restrict__ src = (const float4*)(in  + base);
        float4*       __restrict__ dst = (float4*)(out + base);

        float4 a0 = __ldcs(src + 0 * 32 + lane);
        float4 a1 = __ldcs(src + 1 * 32 + lane);
        float4 a2 = __ldcs(src + 2 * 32 + lane);
        float4 a3 = __ldcs(src + 3 * 32 + lane);

        // inclusive scan inside each 4-element chunk
        a0.y += a0.x; a0.z += a0.y; a0.w += a0.z;
        a1.y += a1.x; a1.z += a1.y; a1.w += a1.z;
        a2.y += a2.x; a2.z += a2.y; a2.w += a2.z;
        a3.y += a3.x; a3.z += a3.y; a3.w += a3.z;

        // warp scans of chunk totals
        const float t0 = a0.w, t1 = a1.w, t2 = a2.w, t3 = a3.w;
        float i0 = warp_incl_scan(t0, lane);
        float i1 = warp_incl_scan(t1, lane);
        float i2 = warp_incl_scan(t2, lane);
        float i3 = warp_incl_scan(t3, lane);
        const float T0 = __shfl_sync(0xffffffffu, i0, 31);
        const float T1 = __shfl_sync(0xffffffffu, i1, 31);
        const float T2 = __shfl_sync(0xffffffffu, i2, 31);

        const float o0 = i0 - t0;
        const float o1 = (i1 - t1) + T0;
        const float o2 = (i2 - t2) + T0 + T1;
        const float o3 = (i3 - t3) + T0 + T1 + T2;

        a0.x += o0; a0.y += o0; a0.z += o0; a0.w += o0;
        a1.x += o1; a1.y += o1; a1.z += o1; a1.w += o1;
        a2.x += o2; a2.y += o2; a2.z += o2; a2.w += o2;
        a3.x += o3; a3.y += o3; a3.z += o3; a3.w += o3;

        __stcs(dst + 0 * 32 + lane, a0);
        __stcs(dst + 1 * 32 + lane, a1);
        __stcs(dst + 2 * 32 + lane, a2);
        __stcs(dst + 3 * 32 + lane, a3);
    }
}

extern "C" void kernel_launch(void* const* d_in, const int* in_sizes, int n_in,
                              void* d_out, int out_size) {
    const float* in  = (const float*)d_in[0];
    float*       out = (float*)d_out;
    grid_spatial_integral_kernel<<<TOTAL_BLOCKS, THREADS>>>(in, out);
}

// round 16
// speedup vs baseline: 1.1031x; 1.1031x over previous
#include <cuda_runtime.h>
#include <cuda_bf16.h>

// GridSpatialIntegral: input [B=64, C=2, WY=512, WX=512] fp32.
//   out[:,0,:,:] = cumsum over x of in[:,0,:,:]
//   out[:,1,:,:] = cumsum over y of in[:,1,:,:]
//
// FINAL CHAMPION (R5; reproduced R10/R11/R13/R14): single fused kernel,
// 512-thread blocks, __launch_bounds__(512, 2) — load-bearing: pins ptxas at
// 48 regs, 2 blocks/SM. Measured 37.5-38.2us kernel, ~7.1 TB/s effective
// (~89% of HBM spec). 9 structural variants tested (deeper MLP pipelines,
// forced occupancy, cp.async staging, role interleaving, duration balancing,
// persistent grid, float2 ch1 @ 1blk/SM) — all regressed.
//   blocks [0, 1024)        : channel-1. Block owns 32 columns x 512 rows.
//                             16 warps; warp w owns 32-row segment w; segment
//                             totals exchanged through smem.
//   blocks [1024, 1024+2048): channel-0 row scans (warp per row, 16 rows/blk),
//                             lane-contiguous float4 loads.

#define B   64
#define WY  512
#define WX  512

#define CH1_BLOCKS 1024                // 32768 columns / 32 per block
#define CH0_BLOCKS 2048                // 32768 rows / 16 warps-per-block
#define TOTAL_BLOCKS (CH1_BLOCKS + CH0_BLOCKS)
#define THREADS 512

__device__ __forceinline__ float warp_incl_scan(float v, int lane) {
    #pragma unroll
    for (int d = 1; d < 32; d <<= 1) {
        float n = __shfl_up_sync(0xffffffffu, v, d);
        if (lane >= d) v += n;
    }
    return v;
}

__global__ __launch_bounds__(THREADS, 2)
void grid_spatial_integral_kernel(const float* __restrict__ in,
                                  float* __restrict__ out) {
    const int bx = blockIdx.x;
    __shared__ float seg_totals[16][32];

    if (bx < CH1_BLOCKS) {
        // ---------------- Channel 1: cumsum along y ----------------
        // block -> (batch, 32-column group). warp -> 32-row segment.
        const int lane = threadIdx.x & 31;
        const int seg  = threadIdx.x >> 5;          // 0..15
        const int b    = bx >> 4;                   // 16 col-groups per batch
        const int xg   = bx & 15;
        const int x    = xg * 32 + lane;            // 0..511

        const int base = ((b * 2 + 1) * WY + seg * 32) * WX + x;
        const float* __restrict__ p = in  + base;
        float*       __restrict__ q = out + base;

        // load 32 rows into registers (coalesced 128B per warp instruction)
        float v[32];
        #pragma unroll
        for (int k = 0; k < 32; ++k)
            v[k] = __ldcs(p + k * WX);

        // in-register inclusive prefix over this segment
        #pragma unroll
        for (int k = 1; k < 32; ++k)
            v[k] += v[k - 1];

        // publish segment total, gather carry from lower segments
        seg_totals[seg][lane] = v[31];
        __syncthreads();

        float carry = 0.0f;
        #pragma unroll
        for (int s = 0; s < 15; ++s)
            if (s < seg) carry += seg_totals[s][lane];

        #pragma unroll
        for (int k = 0; k < 32; ++k)
            __stcs(q + k * WX, v[k] + carry);
    } else {
        // ---------------- Channel 0: cumsum along x ----------------
        // warp per 512-float row. lane-contiguous float4 loads:
        // chunk id c = i*32 + lane holds elements [4c, 4c+4).
        const int idx  = bx - CH1_BLOCKS;           // 0..2047
        const int wid  = threadIdx.x >> 5;          // 0..15
        const int lane = threadIdx.x & 31;
        const int row  = idx * 16 + wid;            // 0..32767
        const int b    = row >> 9;
        const int y    = row & 511;

        const int base = ((b * 2 + 0) * WY + y) * WX;
        const float4* __restrict__ src = (const float4*)(in  + base);
        float4*       __restrict__ dst = (float4*)(out + base);

        float4 a0 = __ldcs(src + 0 * 32 + lane);
        float4 a1 = __ldcs(src + 1 * 32 + lane);
        float4 a2 = __ldcs(src + 2 * 32 + lane);
        float4 a3 = __ldcs(src + 3 * 32 + lane);

        // inclusive scan inside each 4-element chunk
        a0.y += a0.x; a0.z += a0.y; a0.w += a0.z;
        a1.y += a1.x; a1.z += a1.y; a1.w += a1.z;
        a2.y += a2.x; a2.z += a2.y; a2.w += a2.z;
        a3.y += a3.x; a3.z += a3.y; a3.w += a3.z;

        // warp scans of chunk totals, one per chunk-row i
        const float t0 = a0.w, t1 = a1.w, t2 = a2.w, t3 = a3.w;
        float i0 = warp_incl_scan(t0, lane);
        float i1 = warp_incl_scan(t1, lane);
        float i2 = warp_incl_scan(t2, lane);
        float i3 = warp_incl_scan(t3, lane);
        const float T0 = __shfl_sync(0xffffffffu, i0, 31);
        const float T1 = __shfl_sync(0xffffffffu, i1, 31);
        const float T2 = __shfl_sync(0xffffffffu, i2, 31);

        // offset for chunk (i, lane) = sum_{j<i} T_j + excl_i(lane)
        const float o0 = i0 - t0;
        const float o1 = (i1 - t1) + T0;
        const float o2 = (i2 - t2) + T0 + T1;
        const float o3 = (i3 - t3) + T0 + T1 + T2;

        a0.x += o0; a0.y += o0; a0.z += o0; a0.w += o0;
        a1.x += o1; a1.y += o1; a1.z += o1; a1.w += o1;
        a2.x += o2; a2.y += o2; a2.z += o2; a2.w += o2;
        a3.x += o3; a3.y += o3; a3.z += o3; a3.w += o3;

        __stcs(dst + 0 * 32 + lane, a0);
        __stcs(dst + 1 * 32 + lane, a1);
        __stcs(dst + 2 * 32 + lane, a2);
        __stcs(dst + 3 * 32 + lane, a3);
    }
}

extern "C" void kernel_launch(void* const* d_in, const int* in_sizes, int n_in,
                              void* d_out, int out_size) {
    const float* in  = (const float*)d_in[0];
    float*       out = (float*)d_out;
    grid_spatial_integral_kernel<<<TOTAL_BLOCKS, THREADS>>>(in, out);
}

// round 17
// speedup vs baseline: 1.1063x; 1.0029x over previous
#include <cuda_runtime.h>
#include <cuda_bf16.h>

// GridSpatialIntegral: input [B=64, C=2, WY=512, WX=512] fp32.
//   out[:,0,:,:] = cumsum over x of in[:,0,:,:]
//   out[:,1,:,:] = cumsum over y of in[:,1,:,:]
//
// FINAL CHAMPION (R5; reproduced R10/R11/R13/R14/R16): single fused kernel,
// 512-thread blocks, __launch_bounds__(512, 2) — load-bearing: pins ptxas at
// 48 regs, 2 blocks/SM. Measured 37.5-38.2us kernel, ~7.1 TB/s effective
// (~89% of HBM spec) on compulsory 256MB traffic. 9 structural variants
// tested (deeper MLP pipelines, forced occupancy, cp.async staging, role
// interleaving, duration balancing, persistent grid, float2 ch1) — all
// regressed; the 48-reg allocation is the keystone.
//   blocks [0, 1024)        : channel-1. Block owns 32 columns x 512 rows.
//                             16 warps; warp w owns 32-row segment w; segment
//                             totals exchanged through smem.
//   blocks [1024, 1024+2048): channel-0 row scans (warp per row, 16 rows/blk),
//                             lane-contiguous float4 loads.

#define B   64
#define WY  512
#define WX  512

#define CH1_BLOCKS 1024                // 32768 columns / 32 per block
#define CH0_BLOCKS 2048                // 32768 rows / 16 warps-per-block
#define TOTAL_BLOCKS (CH1_BLOCKS + CH0_BLOCKS)
#define THREADS 512

__device__ __forceinline__ float warp_incl_scan(float v, int lane) {
    #pragma unroll
    for (int d = 1; d < 32; d <<= 1) {
        float n = __shfl_up_sync(0xffffffffu, v, d);
        if (lane >= d) v += n;
    }
    return v;
}

__global__ __launch_bounds__(THREADS, 2)
void grid_spatial_integral_kernel(const float* __restrict__ in,
                                  float* __restrict__ out) {
    const int bx = blockIdx.x;
    __shared__ float seg_totals[16][32];

    if (bx < CH1_BLOCKS) {
        // ---------------- Channel 1: cumsum along y ----------------
        // block -> (batch, 32-column group). warp -> 32-row segment.
        const int lane = threadIdx.x & 31;
        const int seg  = threadIdx.x >> 5;          // 0..15
        const int b    = bx >> 4;                   // 16 col-groups per batch
        const int xg   = bx & 15;
        const int x    = xg * 32 + lane;            // 0..511

        const int base = ((b * 2 + 1) * WY + seg * 32) * WX + x;
        const float* __restrict__ p = in  + base;
        float*       __restrict__ q = out + base;

        // load 32 rows into registers (coalesced 128B per warp instruction)
        float v[32];
        #pragma unroll
        for (int k = 0; k < 32; ++k)
            v[k] = __ldcs(p + k * WX);

        // in-register inclusive prefix over this segment
        #pragma unroll
        for (int k = 1; k < 32; ++k)
            v[k] += v[k - 1];

        // publish segment total, gather carry from lower segments
        seg_totals[seg][lane] = v[31];
        __syncthreads();

        float carry = 0.0f;
        #pragma unroll
        for (int s = 0; s < 15; ++s)
            if (s < seg) carry += seg_totals[s][lane];

        #pragma unroll
        for (int k = 0; k < 32; ++k)
            __stcs(q + k * WX, v[k] + carry);
    } else {
        // ---------------- Channel 0: cumsum along x ----------------
        // warp per 512-float row. lane-contiguous float4 loads:
        // chunk id c = i*32 + lane holds elements [4c, 4c+4).
        const int idx  = bx - CH1_BLOCKS;           // 0..2047
        const int wid  = threadIdx.x >> 5;          // 0..15
        const int lane = threadIdx.x & 31;
        const int row  = idx * 16 + wid;            // 0..32767
        const int b    = row >> 9;
        const int y    = row & 511;

        const int base = ((b * 2 + 0) * WY + y) * WX;
        const float4* __restrict__ src = (const float4*)(in  + base);
        float4*       __restrict__ dst = (float4*)(out + base);

        float4 a0 = __ldcs(src + 0 * 32 + lane);
        float4 a1 = __ldcs(src + 1 * 32 + lane);
        float4 a2 = __ldcs(src + 2 * 32 + lane);
        float4 a3 = __ldcs(src + 3 * 32 + lane);

        // inclusive scan inside each 4-element chunk
        a0.y += a0.x; a0.z += a0.y; a0.w += a0.z;
        a1.y += a1.x; a1.z += a1.y; a1.w += a1.z;
        a2.y += a2.x; a2.z += a2.y; a2.w += a2.z;
        a3.y += a3.x; a3.z += a3.y; a3.w += a3.z;

        // warp scans of chunk totals, one per chunk-row i
        const float t0 = a0.w, t1 = a1.w, t2 = a2.w, t3 = a3.w;
        float i0 = warp_incl_scan(t0, lane);
        float i1 = warp_incl_scan(t1, lane);
        float i2 = warp_incl_scan(t2, lane);
        float i3 = warp_incl_scan(t3, lane);
        const float T0 = __shfl_sync(0xffffffffu, i0, 31);
        const float T1 = __shfl_sync(0xffffffffu, i1, 31);
        const float T2 = __shfl_sync(0xffffffffu, i2, 31);

        // offset for chunk (i, lane) = sum_{j<i} T_j + excl_i(lane)
        const float o0 = i0 - t0;
        const float o1 = (i1 - t1) + T0;
        const float o2 = (i2 - t2) + T0 + T1;
        const float o3 = (i3 - t3) + T0 + T1 + T2;

        a0.x += o0; a0.y += o0; a0.z += o0; a0.w += o0;
        a1.x += o1; a1.y += o1; a1.z += o1; a1.w += o1;
        a2.x += o2; a2.y += o2; a2.z += o2; a2.w += o2;
        a3.x += o3; a3.y += o3; a3.z += o3; a3.w += o3;

        __stcs(dst + 0 * 32 + lane, a0);
        __stcs(dst + 1 * 32 + lane, a1);
        __stcs(dst + 2 * 32 + lane, a2);
        __stcs(dst + 3 * 32 + lane, a3);
    }
}

extern "C" void kernel_launch(void* const* d_in, const int* in_sizes, int n_in,
                              void* d_out, int out_size) {
    const float* in  = (const float*)d_in[0];
    float*       out = (float*)d_out;
    grid_spatial_integral_kernel<<<TOTAL_BLOCKS, THREADS>>>(in, out);
}